// round 1
// baseline (speedup 1.0000x reference)
#include <cuda_runtime.h>

// GRU-D on GB300. Problem constants (fixed by the dataset):
#define BATCH 1024
#define LTRUE 96
#define LPRED 24
#define LALL  120
#define NF    64
#define HID   128

// ---------------------------------------------------------------------------
// Device scratch (no allocation allowed in kernel_launch).
// g_W4T [k][j]  : {Wr, Wz, Wn1, Wn2}[j,k]   (recurrent-h weights, merged)
//    Wr[j,k]  = W_ih[j,      64+k] + W_hh[j,      k]
//    Wz[j,k]  = W_ih[128+j,  64+k] + W_hh[128+j,  k]
//    Wn1[j,k] = W_ih[256+j,  64+k]            (gi_n h-part)
//    Wn2[j,k] = W_hh[256+j,  k]               (gr_n, gets multiplied by r)
// g_Wc4T [k][j] : {Cr, Cz, Cn, 0}[j,k]  input-side weights over k in [0,128):
//    k<64  -> x_in columns  W_ih[gate][k]
//    k>=64 -> mask columns  W_ih[gate][128+k]   (cols 192..255)
// g_rep : decayed hidden states for t in [96,120), projected by epilogue.
// ---------------------------------------------------------------------------
__device__ float4 g_W4T [128 * 128];
__device__ float4 g_Wc4T[128 * 128];
__device__ float  g_rep [(size_t)BATCH * LPRED * HID];

// ---------------------------------------------------------------------------
// Prep: build transposed/merged weight tables (16384 float4 pairs).
// ---------------------------------------------------------------------------
__global__ void grud_prep_kernel(const float* __restrict__ W_ih,
                                 const float* __restrict__ W_hh)
{
    int idx = blockIdx.x * blockDim.x + threadIdx.x;
    if (idx >= 128 * 128) return;
    int k = idx >> 7;
    int j = idx & 127;

    float4 w;
    w.x = W_ih[(j      ) * 256 + 64 + k] + W_hh[(j      ) * 128 + k];
    w.y = W_ih[(128 + j) * 256 + 64 + k] + W_hh[(128 + j) * 128 + k];
    w.z = W_ih[(256 + j) * 256 + 64 + k];
    w.w = W_hh[(256 + j) * 128 + k];
    g_W4T[idx] = w;

    int ck = (k < 64) ? k : (128 + k);   // 0..63 -> x_in cols, 64..127 -> mask cols
    float4 c;
    c.x = W_ih[(j      ) * 256 + ck];
    c.y = W_ih[(128 + j) * 256 + ck];
    c.z = W_ih[(256 + j) * 256 + ck];
    c.w = 0.0f;
    g_Wc4T[idx] = c;
}

// ---------------------------------------------------------------------------
// Main recurrent kernel. 128 blocks x 256 threads; block owns 8 batch rows.
// Thread layout:
//   j    = tid & 127  : hidden index owned by this thread
//   half = tid >> 7   : rows half*4 .. half*4+3
// Feature work uses a separate (row, feature) mapping: item = tid + 256*i.
// ---------------------------------------------------------------------------
__global__ __launch_bounds__(256, 1)
void grud_main_kernel(const float* __restrict__ tp_pred,
                      const float* __restrict__ X,
                      const float* __restrict__ tp_true,
                      const float* __restrict__ mask,
                      const float* __restrict__ Wh_dec,
                      const float* __restrict__ bh_dec,
                      const float* __restrict__ Wx_dec,
                      const float* __restrict__ bx_dec,
                      const float* __restrict__ b_ih,
                      const float* __restrict__ b_hh)
{
    __shared__ float s_in[8][128];        // [row][k]: k<64 x_in, k>=64 mask
    __shared__ float s_h [8][128];        // decayed h (== rep)
    __shared__ float s_dt[8][LALL];       // per-row time deltas

    const int tid  = threadIdx.x;
    const int j    = tid & 127;
    const int half = tid >> 7;
    const int b0   = blockIdx.x * 8;

    // ---- per-thread hidden-space constants ----
    float S = 0.0f;                        // rowsum of Wh_dec
    #pragma unroll 8
    for (int n = 0; n < NF; n++) S += Wh_dec[j * NF + n];
    const float bh   = bh_dec[j];
    const float ubr  = b_ih[j]       + b_hh[j];
    const float ubz  = b_ih[128 + j] + b_hh[128 + j];
    const float ubn1 = b_ih[256 + j];          // gi_n bias
    const float ubn2 = b_hh[256 + j];          // gr_n bias (inside r-multiply)

    // ---- per-thread feature items (2 of the 512 (row,feature) slots) ----
    const int it0 = tid, it1 = tid + 256;
    const int r0f = it0 >> 6, n0f = it0 & 63;
    const int r1f = it1 >> 6, n1f = it1 & 63;
    const float wxd0 = Wx_dec[n0f * 64 + n0f];
    const float wxd1 = Wx_dec[n1f * 64 + n1f];
    const float bx0  = bx_dec[n0f];
    const float bx1  = bx_dec[n1f];

    const float* Xb0 = X    + (size_t)(b0 + r0f) * LTRUE * NF + n0f;
    const float* Mb0 = mask + (size_t)(b0 + r0f) * LTRUE * NF + n0f;
    const float* Xb1 = X    + (size_t)(b0 + r1f) * LTRUE * NF + n1f;
    const float* Mb1 = mask + (size_t)(b0 + r1f) * LTRUE * NF + n1f;

    // mu: mean of unmasked X over time; cnt includes the 24 padded steps
    float sum0 = 0.0f, cnt0 = (float)LPRED;
    float sum1 = 0.0f, cnt1 = (float)LPRED;
    for (int t = 0; t < LTRUE; t++) {
        float m0 = Mb0[t * NF], x0 = Xb0[t * NF];
        float m1 = Mb1[t * NF], x1 = Xb1[t * NF];
        sum0 += x0 * (1.0f - m0);  cnt0 += 1.0f - m0;
        sum1 += x1 * (1.0f - m1);  cnt1 += 1.0f - m1;
    }
    const float mu0 = sum0 / fmaxf(cnt0, 1.0f);
    const float mu1 = sum1 / fmaxf(cnt1, 1.0f);
    float xl0 = Xb0[0];                       // LOCF state, init = X[:,0]
    float xl1 = Xb1[0];

    // ---- dt table into smem ----
    for (int it = tid; it < 8 * LALL; it += 256) {
        int r = it / LALL, t = it % LALL;
        int b = b0 + r;
        float d = 0.0f;
        if (t > 0) {
            float a = (t     < LTRUE) ? tp_true[b * LTRUE + t]
                                      : tp_pred[b * LPRED + (t - LTRUE)];
            float p = (t - 1 < LTRUE) ? tp_true[b * LTRUE + (t - 1)]
                                      : tp_pred[b * LPRED + (t - 1 - LTRUE)];
            d = a - p;
        }
        s_dt[r][t] = d;
    }

    float h[4] = {0.0f, 0.0f, 0.0f, 0.0f};
    __syncthreads();

    for (int t = 0; t < LALL; t++) {
        // ---- feature phase: x_in and mask into s_in ----
        {
            float d0 = s_dt[r0f][t], d1 = s_dt[r1f][t];
            float gx0 = __expf(-fmaxf(fmaf(d0, wxd0, bx0), 0.0f));
            float gx1 = __expf(-fmaxf(fmaf(d1, wxd1, bx1), 0.0f));
            float xv0 = 0.0f, mv0 = 0.0f, xv1 = 0.0f, mv1 = 0.0f;
            if (t < LTRUE) {
                xv0 = Xb0[t * NF]; mv0 = Mb0[t * NF];
                xv1 = Xb1[t * NF]; mv1 = Mb1[t * NF];
            }
            // LOCF: cur = (m != 0) ? prev : x   (update first, then use)
            xl0 = (mv0 != 0.0f) ? xl0 : xv0;
            xl1 = (mv1 != 0.0f) ? xl1 : xv1;
            float xh0 = gx0 * xl0 + (1.0f - gx0) * mu0;
            float xh1 = gx1 * xl1 + (1.0f - gx1) * mu1;
            float xi0 = mv0 * xv0 + (1.0f - mv0) * xh0;
            float xi1 = mv1 * xv1 + (1.0f - mv1) * xh1;
            s_in[r0f][n0f]      = xi0;
            s_in[r0f][64 + n0f] = mv0;
            s_in[r1f][n1f]      = xi1;
            s_in[r1f][64 + n1f] = mv1;
        }
        // ---- hidden decay; s_h holds rep (decayed h before GRU update) ----
        #pragma unroll
        for (int rr = 0; rr < 4; rr++) {
            int r = half * 4 + rr;
            float gh = __expf(-fmaxf(fmaf(s_dt[r][t], S, bh), 0.0f));
            h[rr] *= gh;
            s_h[r][j] = h[rr];
        }
        __syncthreads();

        // ---- stream rep for prediction window ----
        if (t >= LTRUE) {
            int tt = t - LTRUE;
            #pragma unroll
            for (int w = 0; w < 4; w++) {
                int idx = tid + 256 * w;          // 0..1023
                int r = idx >> 7, c = idx & 127;
                g_rep[((size_t)(b0 + r) * LPRED + tt) * HID + c] = s_h[r][c];
            }
        }

        // ---- gate GEMM: 4 accumulators x 4 rows, K=128, 7 FFMA/row/k ----
        float aR[4], aZ[4], aN1[4], aN2[4];
        #pragma unroll
        for (int rr = 0; rr < 4; rr++) {
            aR[rr] = ubr; aZ[rr] = ubz; aN1[rr] = ubn1; aN2[rr] = ubn2;
        }
        #pragma unroll 4
        for (int k = 0; k < 128; k++) {
            float4 w4 = g_W4T [(k << 7) + j];
            float4 c4 = g_Wc4T[(k << 7) + j];
            #pragma unroll
            for (int rr = 0; rr < 4; rr++) {
                int r = half * 4 + rr;
                float hv = s_h[r][k];
                float iv = s_in[r][k];
                aR[rr]  = fmaf(w4.x, hv, aR[rr]);
                aR[rr]  = fmaf(c4.x, iv, aR[rr]);
                aZ[rr]  = fmaf(w4.y, hv, aZ[rr]);
                aZ[rr]  = fmaf(c4.y, iv, aZ[rr]);
                aN1[rr] = fmaf(w4.z, hv, aN1[rr]);
                aN1[rr] = fmaf(c4.z, iv, aN1[rr]);
                aN2[rr] = fmaf(w4.w, hv, aN2[rr]);
            }
        }
        // ---- gates + state update ----
        #pragma unroll
        for (int rr = 0; rr < 4; rr++) {
            float rg  = 1.0f / (1.0f + __expf(-aR[rr]));
            float zg  = 1.0f / (1.0f + __expf(-aZ[rr]));
            float pre = fmaf(rg, aN2[rr], aN1[rr]);
            float ng  = 1.0f - 2.0f / (1.0f + __expf(2.0f * pre));  // tanh
            h[rr] = (1.0f - zg) * ng + zg * h[rr];
        }
        __syncthreads();   // protect s_in/s_h/s_dt reads from next iter writes
    }
}

// ---------------------------------------------------------------------------
// Epilogue: out[b, tp, n] = bp[n] + sum_j rep[b,tp,j] * Wp[n,j]
// One block per batch row; Wp and rep tiles staged in smem.
// ---------------------------------------------------------------------------
__global__ __launch_bounds__(256)
void grud_proj_kernel(const float* __restrict__ Wp,
                      const float* __restrict__ bp,
                      float* __restrict__ out)
{
    __shared__ float sWp [64 * 129];      // padded stride to dodge bank conflicts
    __shared__ float sRep[LPRED * HID];   // 3072
    const int b   = blockIdx.x;
    const int tid = threadIdx.x;

    for (int i = tid; i < 64 * 128; i += 256) {
        int n = i >> 7, jj = i & 127;
        sWp[n * 129 + jj] = Wp[i];
    }
    for (int i = tid; i < LPRED * HID; i += 256)
        sRep[i] = g_rep[(size_t)b * LPRED * HID + i];
    __syncthreads();

    #pragma unroll
    for (int q = 0; q < 6; q++) {
        int o  = tid + 256 * q;           // 0..1535
        int tp = o >> 6, n = o & 63;
        float acc = bp[n];
        #pragma unroll 8
        for (int jj = 0; jj < 128; jj++)
            acc = fmaf(sRep[tp * 128 + jj], sWp[n * 129 + jj], acc);
        out[((size_t)b * LPRED + tp) * 64 + n] = acc;
    }
}

// ---------------------------------------------------------------------------
extern "C" void kernel_launch(void* const* d_in, const int* in_sizes, int n_in,
                              void* d_out, int out_size)
{
    const float* tp_pred = (const float*)d_in[0];
    const float* X       = (const float*)d_in[1];
    const float* tp_true = (const float*)d_in[2];
    const float* mask    = (const float*)d_in[3];
    const float* Wh_dec  = (const float*)d_in[4];
    const float* bh_dec  = (const float*)d_in[5];
    const float* Wx_dec  = (const float*)d_in[6];
    const float* bx_dec  = (const float*)d_in[7];
    const float* W_ih    = (const float*)d_in[8];
    const float* W_hh    = (const float*)d_in[9];
    const float* b_ih    = (const float*)d_in[10];
    const float* b_hh    = (const float*)d_in[11];
    const float* Wp      = (const float*)d_in[12];
    const float* bp      = (const float*)d_in[13];
    float* out = (float*)d_out;

    grud_prep_kernel<<<64, 256>>>(W_ih, W_hh);
    grud_main_kernel<<<BATCH / 8, 256>>>(tp_pred, X, tp_true, mask,
                                         Wh_dec, bh_dec, Wx_dec, bx_dec,
                                         b_ih, b_hh);
    grud_proj_kernel<<<BATCH, 256>>>(Wp, bp, out);
}

// round 3
// speedup vs baseline: 1.0512x; 1.0512x over previous
#include <cuda_runtime.h>

// GRU-D on GB300 (sm_103a). Fixed problem sizes:
#define BATCH 1024
#define LTRUE 96
#define LPRED 24
#define LALL  120
#define NF    64
#define HID   128

typedef unsigned long long ull;

// ---------------------------------------------------------------------------
// Packed fp32x2 helpers (Blackwell packed-FMA path; ptxas won't auto-fuse).
// ---------------------------------------------------------------------------
#define FMA2(acc, a, b) \
    asm("fma.rn.f32x2 %0, %1, %2, %0;" : "+l"(acc) : "l"(a), "l"(b))

__device__ __forceinline__ ull pack_dup(float v) {
    ull r; asm("mov.b64 %0, {%1, %1};" : "=l"(r) : "f"(v)); return r;
}
__device__ __forceinline__ ull pack_pair(float a, float b) {
    ull r; asm("mov.b64 %0, {%1, %2};" : "=l"(r) : "f"(a), "f"(b)); return r;
}
__device__ __forceinline__ void unpack2(ull p, float& a, float& b) {
    asm("mov.b64 {%0, %1}, %2;" : "=f"(a), "=f"(b) : "l"(p));
}
__device__ __forceinline__ ull mul2(ull a, ull b) {
    ull r; asm("mul.rn.f32x2 %0, %1, %2;" : "=l"(r) : "l"(a), "l"(b)); return r;
}

// ---------------------------------------------------------------------------
// Device scratch.
// g_WA [k*128+j] : (wR, wZ, cR, cZ)  — R/Z gate weights (streamed from L2)
//    wR = W_ih[j,      64+k] + W_hh[j,      k]
//    wZ = W_ih[128+j,  64+k] + W_hh[128+j,  k]
//    cR/cZ: input-side cols (k<64 -> x_in col k; k>=64 -> mask col 128+k)
// g_WB2[k*128+j] : (wN1, cN1)        — N-gate (resident in smem)
// g_WB1[k*128+j] :  wN2              — gr_n weight (multiplied by r)
// g_rep : decayed hidden states for t in [96,120).
// ---------------------------------------------------------------------------
__device__ float4 g_WA [128 * 128];
__device__ float2 g_WB2[128 * 128];
__device__ float  g_WB1[128 * 128];
__device__ float  g_rep[(size_t)BATCH * LPRED * HID];

// Dynamic shared memory layout (in floats)
#define OFF_SB2  0            // 16384 float2 = 32768 floats (128 KB)
#define OFF_SB1  32768        // 16384 floats (64 KB)
#define OFF_SH   49152        // s_h [k][8]    1024
#define OFF_SIN  50176        // s_in[k][8]    1024
#define OFF_SN1  51200        // N1 preacts [j][8] 1024
#define OFF_SN2  52224        // N2 preacts [j][8] 1024
#define OFF_SDT  53248        // dt [r][120]   960
#define SMEM_FLOATS 54208
#define SMEM_BYTES (SMEM_FLOATS * 4)

// ---------------------------------------------------------------------------
__global__ void grud_prep_kernel(const float* __restrict__ W_ih,
                                 const float* __restrict__ W_hh)
{
    int idx = blockIdx.x * blockDim.x + threadIdx.x;
    if (idx >= 128 * 128) return;
    int k = idx >> 7;
    int j = idx & 127;
    int ck = (k < 64) ? k : (128 + k);

    float4 a;
    a.x = W_ih[(j      ) * 256 + 64 + k] + W_hh[(j      ) * 128 + k];
    a.y = W_ih[(128 + j) * 256 + 64 + k] + W_hh[(128 + j) * 128 + k];
    a.z = W_ih[(j      ) * 256 + ck];
    a.w = W_ih[(128 + j) * 256 + ck];
    g_WA[idx] = a;

    float2 b2;
    b2.x = W_ih[(256 + j) * 256 + 64 + k];
    b2.y = W_ih[(256 + j) * 256 + ck];
    g_WB2[idx] = b2;
    g_WB1[idx] = W_hh[(256 + j) * 128 + k];
}

// ---------------------------------------------------------------------------
// Main recurrent kernel: 128 blocks x 256 threads, 8 batch rows per block.
//   j   = tid & 127 : hidden index
//   grp = tid >> 7  : 0 -> gates R,Z (owns h state); 1 -> gates N1,N2
// Each thread covers ALL 8 rows of its block as 4 packed fp32x2 row-pairs.
// All __syncthreads() are reached unconditionally by every thread.
// ---------------------------------------------------------------------------
__global__ __launch_bounds__(256, 1)
void grud_main_kernel(const float* __restrict__ tp_pred,
                      const float* __restrict__ X,
                      const float* __restrict__ tp_true,
                      const float* __restrict__ mask,
                      const float* __restrict__ Wh_dec,
                      const float* __restrict__ bh_dec,
                      const float* __restrict__ Wx_dec,
                      const float* __restrict__ bx_dec,
                      const float* __restrict__ b_ih,
                      const float* __restrict__ b_hh)
{
    extern __shared__ float smem[];
    float2* sB2  = (float2*)(smem + OFF_SB2);
    float*  sB1  = smem + OFF_SB1;
    float*  s_h  = smem + OFF_SH;
    float*  s_in = smem + OFF_SIN;
    float*  s_n1 = smem + OFF_SN1;
    float*  s_n2 = smem + OFF_SN2;
    float*  s_dt = smem + OFF_SDT;

    const int tid = threadIdx.x;
    const int j   = tid & 127;
    const int grp = tid >> 7;
    const int b0  = blockIdx.x * 8;

    // ---- stage N-gate weight tables into smem (one-time) ----
    for (int i = tid; i < 128 * 128; i += 256) sB2[i] = g_WB2[i];
    for (int i = tid; i < 128 * 128; i += 256) sB1[i] = g_WB1[i];

    // ---- per-thread hidden-space constants ----
    float S = 0.0f;
    #pragma unroll 8
    for (int n = 0; n < NF; n++) S += Wh_dec[j * NF + n];
    const float bh   = bh_dec[j];
    const float ubr  = b_ih[j]       + b_hh[j];
    const float ubz  = b_ih[128 + j] + b_hh[128 + j];
    const float ubn1 = b_ih[256 + j];
    const float ubn2 = b_hh[256 + j];

    // ---- feature items: 2 of the 512 (row,feature) slots per thread ----
    const int it0 = tid, it1 = tid + 256;
    const int r0f = it0 >> 6, n0f = it0 & 63;
    const int r1f = it1 >> 6, n1f = it1 & 63;
    const float wxd0 = Wx_dec[n0f * 64 + n0f];
    const float wxd1 = Wx_dec[n1f * 64 + n1f];
    const float bx0  = bx_dec[n0f];
    const float bx1  = bx_dec[n1f];

    const float* Xb0 = X    + (size_t)(b0 + r0f) * LTRUE * NF + n0f;
    const float* Mb0 = mask + (size_t)(b0 + r0f) * LTRUE * NF + n0f;
    const float* Xb1 = X    + (size_t)(b0 + r1f) * LTRUE * NF + n1f;
    const float* Mb1 = mask + (size_t)(b0 + r1f) * LTRUE * NF + n1f;

    float sum0 = 0.0f, cnt0 = (float)LPRED;
    float sum1 = 0.0f, cnt1 = (float)LPRED;
    for (int t = 0; t < LTRUE; t++) {
        float m0 = Mb0[t * NF], x0 = Xb0[t * NF];
        float m1 = Mb1[t * NF], x1 = Xb1[t * NF];
        sum0 += x0 * (1.0f - m0);  cnt0 += 1.0f - m0;
        sum1 += x1 * (1.0f - m1);  cnt1 += 1.0f - m1;
    }
    const float mu0 = sum0 / fmaxf(cnt0, 1.0f);
    const float mu1 = sum1 / fmaxf(cnt1, 1.0f);
    float xl0 = Xb0[0];
    float xl1 = Xb1[0];

    // ---- dt table ----
    for (int it = tid; it < 8 * LALL; it += 256) {
        int r = it / LALL, t = it % LALL;
        int b = b0 + r;
        float d = 0.0f;
        if (t > 0) {
            float a = (t     < LTRUE) ? tp_true[b * LTRUE + t]
                                      : tp_pred[b * LPRED + (t - LTRUE)];
            float p = (t - 1 < LTRUE) ? tp_true[b * LTRUE + (t - 1)]
                                      : tp_pred[b * LPRED + (t - 1 - LTRUE)];
            d = a - p;
        }
        s_dt[r * LALL + t] = d;
    }

    ull h[4] = {0ull, 0ull, 0ull, 0ull};   // packed row-pairs (grp0 only)
    __syncthreads();

    for (int t = 0; t < LALL; t++) {
        // ======== phase 1: features + hidden decay ========
        {
            float d0 = s_dt[r0f * LALL + t], d1 = s_dt[r1f * LALL + t];
            float gx0 = __expf(-fmaxf(fmaf(d0, wxd0, bx0), 0.0f));
            float gx1 = __expf(-fmaxf(fmaf(d1, wxd1, bx1), 0.0f));
            float xv0 = 0.0f, mv0 = 0.0f, xv1 = 0.0f, mv1 = 0.0f;
            if (t < LTRUE) {
                xv0 = Xb0[t * NF]; mv0 = Mb0[t * NF];
                xv1 = Xb1[t * NF]; mv1 = Mb1[t * NF];
            }
            xl0 = (mv0 != 0.0f) ? xl0 : xv0;
            xl1 = (mv1 != 0.0f) ? xl1 : xv1;
            float xh0 = gx0 * xl0 + (1.0f - gx0) * mu0;
            float xh1 = gx1 * xl1 + (1.0f - gx1) * mu1;
            float xi0 = mv0 * xv0 + (1.0f - mv0) * xh0;
            float xi1 = mv1 * xv1 + (1.0f - mv1) * xh1;
            s_in[n0f * 8 + r0f]        = xi0;   // x_in -> k = n
            s_in[(64 + n0f) * 8 + r0f] = mv0;   // mask -> k = 64+n
            s_in[n1f * 8 + r1f]        = xi1;
            s_in[(64 + n1f) * 8 + r1f] = mv1;
        }
        if (grp == 0) {
            float gh[8];
            #pragma unroll
            for (int r = 0; r < 8; r++)
                gh[r] = __expf(-fmaxf(fmaf(s_dt[r * LALL + t], S, bh), 0.0f));
            #pragma unroll
            for (int p = 0; p < 4; p++)
                h[p] = mul2(h[p], pack_pair(gh[2 * p], gh[2 * p + 1]));
            ulonglong2* ps = (ulonglong2*)(s_h + j * 8);
            ps[0] = make_ulonglong2(h[0], h[1]);
            ps[1] = make_ulonglong2(h[2], h[3]);
        }
        __syncthreads();   // S1 — convergent

        // ======== phase 2: gate GEMM, K = 128 (both groups) ========
        ull aR[4], aZ[4];
        if (grp == 0) {
            const ull ur = pack_dup(ubr), uz = pack_dup(ubz);
            #pragma unroll
            for (int p = 0; p < 4; p++) { aR[p] = ur; aZ[p] = uz; }
            #pragma unroll 4
            for (int k = 0; k < 128; k++) {
                float4 wa = __ldg(&g_WA[(k << 7) + j]);
                ull wr2 = pack_dup(wa.x), wz2 = pack_dup(wa.y);
                ull cr2 = pack_dup(wa.z), cz2 = pack_dup(wa.w);
                ulonglong2 ha = ((const ulonglong2*)(s_h  + k * 8))[0];
                ulonglong2 hb = ((const ulonglong2*)(s_h  + k * 8))[1];
                ulonglong2 ia = ((const ulonglong2*)(s_in + k * 8))[0];
                ulonglong2 ib = ((const ulonglong2*)(s_in + k * 8))[1];
                FMA2(aR[0], wr2, ha.x); FMA2(aR[1], wr2, ha.y);
                FMA2(aR[2], wr2, hb.x); FMA2(aR[3], wr2, hb.y);
                FMA2(aZ[0], wz2, ha.x); FMA2(aZ[1], wz2, ha.y);
                FMA2(aZ[2], wz2, hb.x); FMA2(aZ[3], wz2, hb.y);
                FMA2(aR[0], cr2, ia.x); FMA2(aR[1], cr2, ia.y);
                FMA2(aR[2], cr2, ib.x); FMA2(aR[3], cr2, ib.y);
                FMA2(aZ[0], cz2, ia.x); FMA2(aZ[1], cz2, ia.y);
                FMA2(aZ[2], cz2, ib.x); FMA2(aZ[3], cz2, ib.y);
            }
        } else {
            ull aN1[4], aN2[4];
            const ull u1 = pack_dup(ubn1), u2 = pack_dup(ubn2);
            #pragma unroll
            for (int p = 0; p < 4; p++) { aN1[p] = u1; aN2[p] = u2; }
            #pragma unroll 4
            for (int k = 0; k < 128; k++) {
                float2 wb = sB2[(k << 7) + j];
                float  w1 = sB1[(k << 7) + j];
                ull wn1 = pack_dup(wb.x), cn1 = pack_dup(wb.y), wn2 = pack_dup(w1);
                ulonglong2 ha = ((const ulonglong2*)(s_h  + k * 8))[0];
                ulonglong2 hb = ((const ulonglong2*)(s_h  + k * 8))[1];
                ulonglong2 ia = ((const ulonglong2*)(s_in + k * 8))[0];
                ulonglong2 ib = ((const ulonglong2*)(s_in + k * 8))[1];
                FMA2(aN1[0], wn1, ha.x); FMA2(aN1[1], wn1, ha.y);
                FMA2(aN1[2], wn1, hb.x); FMA2(aN1[3], wn1, hb.y);
                FMA2(aN1[0], cn1, ia.x); FMA2(aN1[1], cn1, ia.y);
                FMA2(aN1[2], cn1, ib.x); FMA2(aN1[3], cn1, ib.y);
                FMA2(aN2[0], wn2, ha.x); FMA2(aN2[1], wn2, ha.y);
                FMA2(aN2[2], wn2, hb.x); FMA2(aN2[3], wn2, hb.y);
            }
            // publish N-gate preactivations
            ulonglong2* p1 = (ulonglong2*)(s_n1 + j * 8);
            p1[0] = make_ulonglong2(aN1[0], aN1[1]);
            p1[1] = make_ulonglong2(aN1[2], aN1[3]);
            ulonglong2* p2 = (ulonglong2*)(s_n2 + j * 8);
            p2[0] = make_ulonglong2(aN2[0], aN2[1]);
            p2[1] = make_ulonglong2(aN2[2], aN2[3]);

            // stream rep (decayed h) for the prediction window
            if (t >= LTRUE) {
                int tt = t - LTRUE;
                #pragma unroll
                for (int r = 0; r < 8; r++)
                    g_rep[((size_t)(b0 + r) * LPRED + tt) * HID + j] =
                        s_h[j * 8 + r];
            }
        }
        __syncthreads();   // S2 — convergent

        // ======== phase 3: activations + h update (grp0 only) ========
        // Safe: grp1 rewrites s_n1/s_n2 only after the NEXT S1, which grp0
        // must also reach; next phase-1 writes touch s_in/s_h only.
        if (grp == 0) {
            ulonglong2 n1a = ((const ulonglong2*)(s_n1 + j * 8))[0];
            ulonglong2 n1b = ((const ulonglong2*)(s_n1 + j * 8))[1];
            ulonglong2 n2a = ((const ulonglong2*)(s_n2 + j * 8))[0];
            ulonglong2 n2b = ((const ulonglong2*)(s_n2 + j * 8))[1];
            ull n1[4] = {n1a.x, n1a.y, n1b.x, n1b.y};
            ull n2[4] = {n2a.x, n2a.y, n2b.x, n2b.y};
            #pragma unroll
            for (int p = 0; p < 4; p++) {
                float ra, rb, za, zb, n1x, n1y, n2x, n2y, hx, hy;
                unpack2(aR[p], ra, rb);
                unpack2(aZ[p], za, zb);
                unpack2(n1[p], n1x, n1y);
                unpack2(n2[p], n2x, n2y);
                unpack2(h[p],  hx,  hy);
                float rg0 = 1.0f / (1.0f + __expf(-ra));
                float rg1 = 1.0f / (1.0f + __expf(-rb));
                float zg0 = 1.0f / (1.0f + __expf(-za));
                float zg1 = 1.0f / (1.0f + __expf(-zb));
                float p0  = fmaf(rg0, n2x, n1x);
                float p1  = fmaf(rg1, n2y, n1y);
                float ng0 = 1.0f - 2.0f / (1.0f + __expf(2.0f * p0));
                float ng1 = 1.0f - 2.0f / (1.0f + __expf(2.0f * p1));
                float h0  = (1.0f - zg0) * ng0 + zg0 * hx;
                float h1  = (1.0f - zg1) * ng1 + zg1 * hy;
                h[p] = pack_pair(h0, h1);
            }
        }
    }
}

// ---------------------------------------------------------------------------
// Epilogue: out[b, tp, n] = bp[n] + sum_j rep[b,tp,j] * Wp[n,j]
// ---------------------------------------------------------------------------
__global__ __launch_bounds__(256)
void grud_proj_kernel(const float* __restrict__ Wp,
                      const float* __restrict__ bp,
                      float* __restrict__ out)
{
    __shared__ float sWp [64 * 129];
    __shared__ float sRep[LPRED * HID];
    const int b   = blockIdx.x;
    const int tid = threadIdx.x;

    for (int i = tid; i < 64 * 128; i += 256) {
        int n = i >> 7, jj = i & 127;
        sWp[n * 129 + jj] = Wp[i];
    }
    for (int i = tid; i < LPRED * HID; i += 256)
        sRep[i] = g_rep[(size_t)b * LPRED * HID + i];
    __syncthreads();

    #pragma unroll
    for (int q = 0; q < 6; q++) {
        int o  = tid + 256 * q;
        int tp = o >> 6, n = o & 63;
        float acc = bp[n];
        #pragma unroll 8
        for (int jj = 0; jj < 128; jj++)
            acc = fmaf(sRep[tp * 128 + jj], sWp[n * 129 + jj], acc);
        out[((size_t)b * LPRED + tp) * 64 + n] = acc;
    }
}

// ---------------------------------------------------------------------------
extern "C" void kernel_launch(void* const* d_in, const int* in_sizes, int n_in,
                              void* d_out, int out_size)
{
    const float* tp_pred = (const float*)d_in[0];
    const float* X       = (const float*)d_in[1];
    const float* tp_true = (const float*)d_in[2];
    const float* mask    = (const float*)d_in[3];
    const float* Wh_dec  = (const float*)d_in[4];
    const float* bh_dec  = (const float*)d_in[5];
    const float* Wx_dec  = (const float*)d_in[6];
    const float* bx_dec  = (const float*)d_in[7];
    const float* W_ih    = (const float*)d_in[8];
    const float* W_hh    = (const float*)d_in[9];
    const float* b_ih    = (const float*)d_in[10];
    const float* b_hh    = (const float*)d_in[11];
    const float* Wp      = (const float*)d_in[12];
    const float* bp      = (const float*)d_in[13];
    float* out = (float*)d_out;

    cudaFuncSetAttribute(grud_main_kernel,
                         cudaFuncAttributeMaxDynamicSharedMemorySize,
                         SMEM_BYTES);

    grud_prep_kernel<<<64, 256>>>(W_ih, W_hh);
    grud_main_kernel<<<BATCH / 8, 256, SMEM_BYTES>>>(
        tp_pred, X, tp_true, mask,
        Wh_dec, bh_dec, Wx_dec, bx_dec, b_ih, b_hh);
    grud_proj_kernel<<<BATCH, 256>>>(Wp, bp, out);
}